// round 14
// baseline (speedup 1.0000x reference)
#include <cuda_runtime.h>
#include <math.h>

#define BN 512
#define TD 2048
#define SD 768
#define HD 128

typedef unsigned long long ull;

// Scratch (device globals — no allocations allowed)
__device__ float g_tpp[32 * BN * HD];   // teacher proj partials (KLEN=64)
__device__ float g_spp[12 * BN * HD];   // student proj partials
__device__ float g_tp[BN * HD];
__device__ float g_sp[BN * HD];
// Transposed U/V: [h][row]
__device__ float g_UtT[HD * BN];
__device__ float g_VtT[HD * BN];
__device__ float g_UsT[HD * BN];
__device__ float g_VsT[HD * BN];
// Partial pre-sigmoid dots: [net*4 + hsplit][BN*BN]  (8 MB)
__device__ float g_pd[8][BN * BN];

// ---- packed f32x2 helpers (sm_100+) --------------------------------------
__device__ __forceinline__ ull pk2(float a, float b) {
    ull r; asm("mov.b64 %0, {%1, %2};" : "=l"(r) : "f"(a), "f"(b)); return r;
}
__device__ __forceinline__ float2 unpk2(ull v) {
    float2 r; asm("mov.b64 {%0, %1}, %2;" : "=f"(r.x), "=f"(r.y) : "l"(v)); return r;
}
__device__ __forceinline__ void fma2(ull &acc, ull a, ull b) {
    asm("fma.rn.f32x2 %0, %1, %2, %0;" : "+l"(acc) : "l"(a), "l"(b));
}
// acc += relu(a + b) * w (packed 2xfp32) — R4-champion formulation.
__device__ __forceinline__ void rfma2(ull &acc, ull a, ull b, ull w) {
    asm("{\n\t"
        ".reg .b64 t;\n\t"
        ".reg .f32 tl, th;\n\t"
        "add.rn.f32x2 t, %1, %2;\n\t"
        "mov.b64 {tl, th}, t;\n\t"
        "max.f32 tl, tl, 0f00000000;\n\t"
        "max.f32 th, th, 0f00000000;\n\t"
        "mov.b64 t, {tl, th};\n\t"
        "fma.rn.f32x2 %0, t, %3, %0;\n\t"
        "}"
        : "+l"(acc) : "l"(a), "l"(b), "l"(w));
}

// ---------------------------------------------------------------------------
// Projection GEMM partials. z=0 teacher (32 k-splits), z=1 student (12).
// KLEN=64, KC=32. Block: 32 rows x 128 cols, 256 threads, micro 2r x 8c
// (8 packed acc chains, ~45 regs -> 5 blocks/SM, 38 warps/SM).
// ---------------------------------------------------------------------------
__global__ void __launch_bounds__(256)
proj_gemm(const float* __restrict__ T, const float* __restrict__ Wt,
          const float* __restrict__ S, const float* __restrict__ Ws) {
    const int KC = 32;
    const int XP = 36;
    __shared__ __align__(16) float Xst[KC * XP];      // [k][r] transposed
    __shared__ __align__(16) float Wsm[KC * HD];      // [kk][c]

    int z = blockIdx.z;
    int ky = blockIdx.y;
    const float* X; const float* W; float* outp; int ldx;
    if (z == 0) { X = T; W = Wt; ldx = TD; outp = g_tpp + ky * (BN * HD); }
    else {
        if (ky >= 12) return;
        X = S; W = Ws; ldx = SD; outp = g_spp + ky * (BN * HD);
    }

    int tid = threadIdx.x;        // 256
    int tx = tid & 15;            // cols tx*8..+7
    int ty = tid >> 4;            // rows ty*2..+1 (0..15)
    int row0 = blockIdx.x * 32;
    int k0 = ky * 64;

    ull acc[2][4];                // [row m][colpair q]
#pragma unroll
    for (int m = 0; m < 2; m++)
#pragma unroll
        for (int q = 0; q < 4; q++) acc[m][q] = 0ull;

#pragma unroll
    for (int kc = 0; kc < 64; kc += KC) {
        // stage X tile 32r x 32k transposed (256 f4, 1/thread)
        {
            int r = tid >> 3, k4 = (tid & 7) * 4;
            float4 v = *reinterpret_cast<const float4*>(
                &X[(row0 + r) * ldx + k0 + kc + k4]);
            Xst[(k4 + 0) * XP + r] = v.x;
            Xst[(k4 + 1) * XP + r] = v.y;
            Xst[(k4 + 2) * XP + r] = v.z;
            Xst[(k4 + 3) * XP + r] = v.w;
        }
        // stage W tile 32k x 128c (1024 f4, 4/thread)
#pragma unroll
        for (int t = 0; t < 4; t++) {
            int i4 = tid + t * 256;
            int kk = i4 >> 5, c4 = (i4 & 31) * 4;
            float4 v = *reinterpret_cast<const float4*>(
                &W[(k0 + kc + kk) * HD + c4]);
            *reinterpret_cast<float4*>(&Wsm[kk * HD + c4]) = v;
        }
        __syncthreads();
#pragma unroll 8
        for (int kk = 0; kk < KC; kk++) {
            float2 a2 = *reinterpret_cast<const float2*>(&Xst[kk * XP + ty * 2]);
            ulonglong2 b01 = *reinterpret_cast<const ulonglong2*>(&Wsm[kk * HD + tx * 8]);
            ulonglong2 b23 = *reinterpret_cast<const ulonglong2*>(&Wsm[kk * HD + tx * 8 + 4]);
            ull a0 = pk2(a2.x, a2.x), a1 = pk2(a2.y, a2.y);
            fma2(acc[0][0], a0, b01.x); fma2(acc[0][1], a0, b01.y);
            fma2(acc[0][2], a0, b23.x); fma2(acc[0][3], a0, b23.y);
            fma2(acc[1][0], a1, b01.x); fma2(acc[1][1], a1, b01.y);
            fma2(acc[1][2], a1, b23.x); fma2(acc[1][3], a1, b23.y);
        }
        __syncthreads();
    }
#pragma unroll
    for (int m = 0; m < 2; m++) {
        int row = row0 + ty * 2 + m;
        float2 q0 = unpk2(acc[m][0]);
        float2 q1 = unpk2(acc[m][1]);
        float2 q2 = unpk2(acc[m][2]);
        float2 q3 = unpk2(acc[m][3]);
        *reinterpret_cast<float4*>(&outp[row * HD + tx * 8]) =
            make_float4(q0.x, q0.y, q1.x, q1.y);
        *reinterpret_cast<float4*>(&outp[row * HD + tx * 8 + 4]) =
            make_float4(q2.x, q2.y, q3.x, q3.y);
    }
}

// ---------------------------------------------------------------------------
// Sum proj partials + bias -> g_tp / g_sp. Grid 128 x 256 thr.
// Also zeroes the output scalar (block 0). (R4 champion, verbatim.)
// ---------------------------------------------------------------------------
__global__ void __launch_bounds__(256)
sumtp(const float* __restrict__ bt, const float* __restrict__ bs,
      float* __restrict__ out, int out_size) {
    if (blockIdx.x == 0) {
        for (int i = threadIdx.x; i < out_size; i += 256) out[i] = 0.0f;
    }
    int b = blockIdx.x;
    int teacher = (b < 64);
    int i4 = (teacher ? b : b - 64) * 256 + threadIdx.x;
    int k4 = (i4 & 31) * 4;
    const float* bias = teacher ? bt : bs;
    const float* pbase = teacher ? g_tpp : g_spp;
    int np = teacher ? 32 : 12;

    float4 a0 = *reinterpret_cast<const float4*>(&bias[k4]);
    float4 a1 = make_float4(0.f, 0.f, 0.f, 0.f);
    float4 a2 = make_float4(0.f, 0.f, 0.f, 0.f);
    float4 a3 = make_float4(0.f, 0.f, 0.f, 0.f);
    for (int p = 0; p < np; p += 4) {
        float4 v0 = *reinterpret_cast<const float4*>(&pbase[(p + 0) * (BN * HD) + i4 * 4]);
        float4 v1 = *reinterpret_cast<const float4*>(&pbase[(p + 1) * (BN * HD) + i4 * 4]);
        float4 v2 = *reinterpret_cast<const float4*>(&pbase[(p + 2) * (BN * HD) + i4 * 4]);
        float4 v3 = *reinterpret_cast<const float4*>(&pbase[(p + 3) * (BN * HD) + i4 * 4]);
        a0.x += v0.x; a0.y += v0.y; a0.z += v0.z; a0.w += v0.w;
        a1.x += v1.x; a1.y += v1.y; a1.z += v1.z; a1.w += v1.w;
        a2.x += v2.x; a2.y += v2.y; a2.z += v2.z; a2.w += v2.w;
        a3.x += v3.x; a3.y += v3.y; a3.z += v3.z; a3.w += v3.w;
    }
    float4 r = make_float4(a0.x + a1.x + a2.x + a3.x,
                           a0.y + a1.y + a2.y + a3.y,
                           a0.z + a1.z + a2.z + a3.z,
                           a0.w + a1.w + a2.w + a3.w);
    float* dst = teacher ? g_tp : g_sp;
    *reinterpret_cast<float4*>(&dst[i4 * 4]) = r;
}

// ---------------------------------------------------------------------------
// U/V projections -> TRANSPOSED outputs [h][row]. (R4 champion, verbatim.)
// grid (16 rowblocks of 32, 4 mats), 256 thr. Micro 4r x 4c.
// ---------------------------------------------------------------------------
__global__ void __launch_bounds__(256)
uv_gemm(const float* __restrict__ W1, const float* __restrict__ b1) {
    const int XP = 36;
    const int WP = 132;
    __shared__ __align__(16) float Xst[HD * XP];
    __shared__ __align__(16) float Wsm[32 * WP];

    int which = blockIdx.y;
    const float* X = (which < 2) ? g_tp : g_sp;
    const float* W = W1 + ((which & 1) ? HD * HD : 0);
    float* outT = (which == 0) ? g_UtT : (which == 1) ? g_VtT
                : (which == 2) ? g_UsT : g_VsT;
    bool add_bias = ((which & 1) == 0);

    int tid = threadIdx.x;       // 256
    int rowsel = tid & 7;        // rows rowsel*4..+3
    int colsel = tid >> 3;       // cols colsel*4..+3
    int r0 = blockIdx.x * 32;

#pragma unroll
    for (int t = 0; t < 4; t++) {
        int i4 = tid + t * 256;
        int r = i4 >> 5, k4 = (i4 & 31) * 4;
        float4 v = *reinterpret_cast<const float4*>(&X[(r0 + r) * HD + k4]);
        Xst[(k4 + 0) * XP + r] = v.x;
        Xst[(k4 + 1) * XP + r] = v.y;
        Xst[(k4 + 2) * XP + r] = v.z;
        Xst[(k4 + 3) * XP + r] = v.w;
    }

    ull acc[4][2];   // [col][rowpair]
#pragma unroll
    for (int c = 0; c < 4; c++) { acc[c][0] = 0ull; acc[c][1] = 0ull; }

    for (int kc = 0; kc < HD; kc += 32) {
        __syncthreads();
#pragma unroll
        for (int t = 0; t < 4; t++) {
            int i4 = tid + t * 256;
            int kk = i4 >> 5, c4 = (i4 & 31) * 4;
            float4 v = *reinterpret_cast<const float4*>(&W[(kc + kk) * HD + c4]);
            *reinterpret_cast<float4*>(&Wsm[kk * WP + c4]) = v;
        }
        __syncthreads();
#pragma unroll 8
        for (int kk = 0; kk < 32; kk++) {
            int k = kc + kk;
            float2 a01 = *reinterpret_cast<const float2*>(&Xst[k * XP + rowsel * 4]);
            float2 a23 = *reinterpret_cast<const float2*>(&Xst[k * XP + rowsel * 4 + 2]);
            float4 w4 = *reinterpret_cast<const float4*>(&Wsm[kk * WP + colsel * 4]);
            ull ap0 = pk2(a01.x, a01.y), ap1 = pk2(a23.x, a23.y);
            ull w0 = pk2(w4.x, w4.x), w1 = pk2(w4.y, w4.y);
            ull w2d = pk2(w4.z, w4.z), w3 = pk2(w4.w, w4.w);
            fma2(acc[0][0], ap0, w0); fma2(acc[0][1], ap1, w0);
            fma2(acc[1][0], ap0, w1); fma2(acc[1][1], ap1, w1);
            fma2(acc[2][0], ap0, w2d); fma2(acc[2][1], ap1, w2d);
            fma2(acc[3][0], ap0, w3); fma2(acc[3][1], ap1, w3);
        }
    }

#pragma unroll
    for (int c = 0; c < 4; c++) {
        int col = colsel * 4 + c;
        float bias = add_bias ? b1[col] : 0.0f;
        float2 v0 = unpk2(acc[c][0]);
        float2 v1 = unpk2(acc[c][1]);
        float4 r = make_float4(v0.x + bias, v0.y + bias,
                               v1.x + bias, v1.y + bias);
        *reinterpret_cast<float4*>(&outT[col * BN + r0 + rowsel * 4]) = r;
    }
}

// ---------------------------------------------------------------------------
// Pairwise partial dots. (R4 champion 11.8us kernel, verbatim.)
// zz = net*4 + hsplit (HC=32). Tile 32(i) x 64(j), grid (8,16,8), 128 thr,
// micro 4i x 4j with rfma2; inputs transposed [h][row].
// ---------------------------------------------------------------------------
__global__ void __launch_bounds__(128)
pairwise_part(const float* __restrict__ w2) {
    const int HC = 32;
    const int US = 36;
    const int VS = 68;
    __shared__ __align__(16) float sU[HC * US];   // [h][i-row]
    __shared__ __align__(16) float sV[HC * VS];   // [h][j-row]
    __shared__ __align__(8)  float2 swd[HC];

    int zz = blockIdx.z;
    int net = zz >> 2;
    int hc = (zz & 3) * HC;
    const float* UT = net ? g_UsT : g_UtT;
    const float* VT = net ? g_VsT : g_VtT;
    float* pd = g_pd[zz];

    int tid = threadIdx.x;       // 128
    int tx = tid & 15;           // j = jbase + tx*4 + n
    int ty = tid >> 4;           // i = ibase + ty*4 + m
    int jbase = blockIdx.x * 64;
    int ibase = blockIdx.y * 32;

    // stage U tile: [h][r] (coalesced LDG, conflict-free STS)
#pragma unroll
    for (int t = 0; t < 8; t++) {
        int i = tid + t * 128;            // 1024: h = i>>5, r = i&31
        int h = i >> 5, r = i & 31;
        sU[h * US + r] = UT[(hc + h) * BN + ibase + r];
    }
#pragma unroll
    for (int t = 0; t < 16; t++) {
        int i = tid + t * 128;            // 2048: h = i>>6, r = i&63
        int h = i >> 6, r = i & 63;
        sV[h * VS + r] = VT[(hc + h) * BN + jbase + r];
    }
    if (tid < HC) { float w = w2[hc + tid]; swd[tid] = make_float2(w, w); }
    __syncthreads();

    ull acc[4][2];               // [n][i-pair]
#pragma unroll
    for (int n = 0; n < 4; n++) { acc[n][0] = 0ull; acc[n][1] = 0ull; }

#pragma unroll 8
    for (int h = 0; h < HC; h++) {
        ulonglong2 up = *reinterpret_cast<const ulonglong2*>(&sU[h * US + ty * 4]);
        float4 v4 = *reinterpret_cast<const float4*>(&sV[h * VS + tx * 4]);
        ull wd = *reinterpret_cast<const ull*>(&swd[h]);
        ull vd0 = pk2(v4.x, v4.x);
        ull vd1 = pk2(v4.y, v4.y);
        ull vd2 = pk2(v4.z, v4.z);
        ull vd3 = pk2(v4.w, v4.w);
        rfma2(acc[0][0], up.x, vd0, wd); rfma2(acc[0][1], up.y, vd0, wd);
        rfma2(acc[1][0], up.x, vd1, wd); rfma2(acc[1][1], up.y, vd1, wd);
        rfma2(acc[2][0], up.x, vd2, wd); rfma2(acc[2][1], up.y, vd2, wd);
        rfma2(acc[3][0], up.x, vd3, wd); rfma2(acc[3][1], up.y, vd3, wd);
    }

    float sums[4][4];            // [m][n]
#pragma unroll
    for (int n = 0; n < 4; n++) {
#pragma unroll
        for (int p = 0; p < 2; p++) {
            float2 v = unpk2(acc[n][p]);
            sums[p * 2 + 0][n] = v.x;
            sums[p * 2 + 1][n] = v.y;
        }
    }
#pragma unroll
    for (int m = 0; m < 4; m++) {
        int i = ibase + ty * 4 + m;
        *reinterpret_cast<float4*>(&pd[i * BN + jbase + tx * 4]) =
            make_float4(sums[m][0], sums[m][1], sums[m][2], sums[m][3]);
    }
}

// ---------------------------------------------------------------------------
// Reduce: rel = sigmoid(sum of 4 h-partials + b2) per net, diag skipped,
// MSE atomically accumulated into out. Loads front-batched for MLP=8.
// ---------------------------------------------------------------------------
__global__ void __launch_bounds__(256)
reduce_kernel(const float* __restrict__ b2v, float* __restrict__ out) {
    __shared__ float sred[256];
    int g = blockIdx.x * 256 + threadIdx.x;     // 65536 groups of 4
    int i = g >> 7;
    int j0 = (g & 127) * 4;
    float b2 = b2v[0];

    float4 t0 = *reinterpret_cast<const float4*>(&g_pd[0][g * 4]);
    float4 t1 = *reinterpret_cast<const float4*>(&g_pd[1][g * 4]);
    float4 t2 = *reinterpret_cast<const float4*>(&g_pd[2][g * 4]);
    float4 t3 = *reinterpret_cast<const float4*>(&g_pd[3][g * 4]);
    float4 s0 = *reinterpret_cast<const float4*>(&g_pd[4][g * 4]);
    float4 s1 = *reinterpret_cast<const float4*>(&g_pd[5][g * 4]);
    float4 s2 = *reinterpret_cast<const float4*>(&g_pd[6][g * 4]);
    float4 s3 = *reinterpret_cast<const float4*>(&g_pd[7][g * 4]);

    float tv[4] = {(t0.x + t1.x) + (t2.x + t3.x),
                   (t0.y + t1.y) + (t2.y + t3.y),
                   (t0.z + t1.z) + (t2.z + t3.z),
                   (t0.w + t1.w) + (t2.w + t3.w)};
    float sv[4] = {(s0.x + s1.x) + (s2.x + s3.x),
                   (s0.y + s1.y) + (s2.y + s3.y),
                   (s0.z + s1.z) + (s2.z + s3.z),
                   (s0.w + s1.w) + (s2.w + s3.w)};
    float local = 0.0f;
#pragma unroll
    for (int n = 0; n < 4; n++) {
        if (i == j0 + n) continue;   // diagonal: rel defined 0 in both
        float rt = 1.0f / (1.0f + __expf(-(tv[n] + b2)));
        float rs = 1.0f / (1.0f + __expf(-(sv[n] + b2)));
        float d = rs - rt;
        local = fmaf(d, d, local);
    }

    sred[threadIdx.x] = local;
    __syncthreads();
    for (int st = 128; st > 0; st >>= 1) {
        if (threadIdx.x < st) sred[threadIdx.x] += sred[threadIdx.x + st];
        __syncthreads();
    }
    if (threadIdx.x == 0)
        atomicAdd(out, sred[0] * (1.0f / ((float)BN * (float)BN)));
}

// ---------------------------------------------------------------------------
extern "C" void kernel_launch(void* const* d_in, const int* in_sizes, int n_in,
                              void* d_out, int out_size) {
    const float* teacher = (const float*)d_in[0];
    const float* student = (const float*)d_in[1];
    const float* Wt = (const float*)d_in[2];
    const float* bt = (const float*)d_in[3];
    const float* Wsw = (const float*)d_in[4];
    const float* bs = (const float*)d_in[5];
    const float* W1 = (const float*)d_in[6];
    const float* b1 = (const float*)d_in[7];
    const float* W2 = (const float*)d_in[8];
    const float* b2 = (const float*)d_in[9];
    float* out = (float*)d_out;

    proj_gemm<<<dim3(16, 32, 2), 256>>>(teacher, Wt, student, Wsw);
    sumtp<<<128, 256>>>(bt, bs, out, out_size);
    uv_gemm<<<dim3(16, 4), 256>>>(W1, b1);
    pairwise_part<<<dim3(8, 16, 8), 128>>>(W2);
    reduce_kernel<<<256, 256>>>(b2, out);
}

// round 15
// speedup vs baseline: 1.1105x; 1.1105x over previous
#include <cuda_runtime.h>
#include <math.h>

#define BN 512
#define TD 2048
#define SD 768
#define HD 128

typedef unsigned long long ull;

// Scratch (device globals — no allocations allowed)
__device__ float g_tpp[32 * BN * HD];   // teacher proj partials (KLEN=64)
__device__ float g_spp[12 * BN * HD];   // student proj partials
__device__ float g_tp[BN * HD];
__device__ float g_sp[BN * HD];
// Transposed U/V: [h][row]
__device__ float g_UtT[HD * BN];
__device__ float g_VtT[HD * BN];
__device__ float g_UsT[HD * BN];
__device__ float g_VsT[HD * BN];
// Partial pre-sigmoid dots: [net*4 + hsplit][BN*BN]  (8 MB)
__device__ float g_pd[8][BN * BN];
// Per-tile completion counters (128 tiles), zeroed by sumtp each launch
__device__ unsigned int g_cnt[128];

// ---- packed f32x2 helpers (sm_100+) --------------------------------------
__device__ __forceinline__ ull pk2(float a, float b) {
    ull r; asm("mov.b64 %0, {%1, %2};" : "=l"(r) : "f"(a), "f"(b)); return r;
}
__device__ __forceinline__ float2 unpk2(ull v) {
    float2 r; asm("mov.b64 {%0, %1}, %2;" : "=f"(r.x), "=f"(r.y) : "l"(v)); return r;
}
__device__ __forceinline__ void fma2(ull &acc, ull a, ull b) {
    asm("fma.rn.f32x2 %0, %1, %2, %0;" : "+l"(acc) : "l"(a), "l"(b));
}
// acc += relu(a + b) * w (packed 2xfp32) — R4-champion formulation.
__device__ __forceinline__ void rfma2(ull &acc, ull a, ull b, ull w) {
    asm("{\n\t"
        ".reg .b64 t;\n\t"
        ".reg .f32 tl, th;\n\t"
        "add.rn.f32x2 t, %1, %2;\n\t"
        "mov.b64 {tl, th}, t;\n\t"
        "max.f32 tl, tl, 0f00000000;\n\t"
        "max.f32 th, th, 0f00000000;\n\t"
        "mov.b64 t, {tl, th};\n\t"
        "fma.rn.f32x2 %0, t, %3, %0;\n\t"
        "}"
        : "+l"(acc) : "l"(a), "l"(b), "l"(w));
}

// ---------------------------------------------------------------------------
// Projection GEMM partials. z=0 teacher (32 k-splits), z=1 student (12).
// KLEN=64, KC=32. Block: 32 rows x 128 cols, 128 thr, micro 4r x 8c.
// (R4 champion, verbatim — measured 20.3us, issue-bound but best known.)
// ---------------------------------------------------------------------------
__global__ void __launch_bounds__(128)
proj_gemm(const float* __restrict__ T, const float* __restrict__ Wt,
          const float* __restrict__ S, const float* __restrict__ Ws) {
    const int KC = 32;
    const int XP = 36;
    __shared__ __align__(16) float Xst[KC * XP];      // [k][r] transposed
    __shared__ __align__(16) float Wsm[KC * HD];      // [kk][c]

    int z = blockIdx.z;
    int ky = blockIdx.y;
    const float* X; const float* W; float* outp; int ldx;
    if (z == 0) { X = T; W = Wt; ldx = TD; outp = g_tpp + ky * (BN * HD); }
    else {
        if (ky >= 12) return;
        X = S; W = Ws; ldx = SD; outp = g_spp + ky * (BN * HD);
    }

    int tid = threadIdx.x;        // 128
    int tx = tid & 15;            // cols tx*8..+7
    int ty = tid >> 4;            // rows ty*4..+3
    int row0 = blockIdx.x * 32;
    int k0 = ky * 64;

    ull acc[4][4];                // [colpair q][row m]
#pragma unroll
    for (int q = 0; q < 4; q++)
#pragma unroll
        for (int m = 0; m < 4; m++) acc[q][m] = 0ull;

#pragma unroll
    for (int kc = 0; kc < 64; kc += KC) {
#pragma unroll
        for (int t = 0; t < 2; t++) {
            int i4 = tid + t * 128;
            int r = i4 >> 3, k4 = (i4 & 7) * 4;
            float4 v = *reinterpret_cast<const float4*>(
                &X[(row0 + r) * ldx + k0 + kc + k4]);
            Xst[(k4 + 0) * XP + r] = v.x;
            Xst[(k4 + 1) * XP + r] = v.y;
            Xst[(k4 + 2) * XP + r] = v.z;
            Xst[(k4 + 3) * XP + r] = v.w;
        }
#pragma unroll
        for (int t = 0; t < 8; t++) {
            int i4 = tid + t * 128;
            int kk = i4 >> 5, c4 = (i4 & 31) * 4;
            float4 v = *reinterpret_cast<const float4*>(
                &W[(k0 + kc + kk) * HD + c4]);
            *reinterpret_cast<float4*>(&Wsm[kk * HD + c4]) = v;
        }
        __syncthreads();
#pragma unroll 8
        for (int kk = 0; kk < KC; kk++) {
            float4 a4 = *reinterpret_cast<const float4*>(&Xst[kk * XP + ty * 4]);
            ulonglong2 b01 = *reinterpret_cast<const ulonglong2*>(&Wsm[kk * HD + tx * 8]);
            ulonglong2 b23 = *reinterpret_cast<const ulonglong2*>(&Wsm[kk * HD + tx * 8 + 4]);
            ull a0 = pk2(a4.x, a4.x), a1 = pk2(a4.y, a4.y);
            ull a2 = pk2(a4.z, a4.z), a3 = pk2(a4.w, a4.w);
            fma2(acc[0][0], a0, b01.x); fma2(acc[0][1], a1, b01.x);
            fma2(acc[0][2], a2, b01.x); fma2(acc[0][3], a3, b01.x);
            fma2(acc[1][0], a0, b01.y); fma2(acc[1][1], a1, b01.y);
            fma2(acc[1][2], a2, b01.y); fma2(acc[1][3], a3, b01.y);
            fma2(acc[2][0], a0, b23.x); fma2(acc[2][1], a1, b23.x);
            fma2(acc[2][2], a2, b23.x); fma2(acc[2][3], a3, b23.x);
            fma2(acc[3][0], a0, b23.y); fma2(acc[3][1], a1, b23.y);
            fma2(acc[3][2], a2, b23.y); fma2(acc[3][3], a3, b23.y);
        }
        __syncthreads();
    }
#pragma unroll
    for (int m = 0; m < 4; m++) {
        int row = row0 + ty * 4 + m;
        float2 q0 = unpk2(acc[0][m]);
        float2 q1 = unpk2(acc[1][m]);
        float2 q2 = unpk2(acc[2][m]);
        float2 q3 = unpk2(acc[3][m]);
        *reinterpret_cast<float4*>(&outp[row * HD + tx * 8]) =
            make_float4(q0.x, q0.y, q1.x, q1.y);
        *reinterpret_cast<float4*>(&outp[row * HD + tx * 8 + 4]) =
            make_float4(q2.x, q2.y, q3.x, q3.y);
    }
}

// ---------------------------------------------------------------------------
// Sum proj partials + bias -> g_tp / g_sp. Grid 128 x 256 thr.
// Block 0 also zeroes the output scalar and the tile counters.
// ---------------------------------------------------------------------------
__global__ void __launch_bounds__(256)
sumtp(const float* __restrict__ bt, const float* __restrict__ bs,
      float* __restrict__ out, int out_size) {
    if (blockIdx.x == 0) {
        for (int i = threadIdx.x; i < out_size; i += 256) out[i] = 0.0f;
        if (threadIdx.x < 128) g_cnt[threadIdx.x] = 0u;
    }
    int b = blockIdx.x;
    int teacher = (b < 64);
    int i4 = (teacher ? b : b - 64) * 256 + threadIdx.x;
    int k4 = (i4 & 31) * 4;
    const float* bias = teacher ? bt : bs;
    const float* pbase = teacher ? g_tpp : g_spp;
    int np = teacher ? 32 : 12;

    float4 a0 = *reinterpret_cast<const float4*>(&bias[k4]);
    float4 a1 = make_float4(0.f, 0.f, 0.f, 0.f);
    float4 a2 = make_float4(0.f, 0.f, 0.f, 0.f);
    float4 a3 = make_float4(0.f, 0.f, 0.f, 0.f);
    for (int p = 0; p < np; p += 4) {
        float4 v0 = *reinterpret_cast<const float4*>(&pbase[(p + 0) * (BN * HD) + i4 * 4]);
        float4 v1 = *reinterpret_cast<const float4*>(&pbase[(p + 1) * (BN * HD) + i4 * 4]);
        float4 v2 = *reinterpret_cast<const float4*>(&pbase[(p + 2) * (BN * HD) + i4 * 4]);
        float4 v3 = *reinterpret_cast<const float4*>(&pbase[(p + 3) * (BN * HD) + i4 * 4]);
        a0.x += v0.x; a0.y += v0.y; a0.z += v0.z; a0.w += v0.w;
        a1.x += v1.x; a1.y += v1.y; a1.z += v1.z; a1.w += v1.w;
        a2.x += v2.x; a2.y += v2.y; a2.z += v2.z; a2.w += v2.w;
        a3.x += v3.x; a3.y += v3.y; a3.z += v3.z; a3.w += v3.w;
    }
    float4 r = make_float4(a0.x + a1.x + a2.x + a3.x,
                           a0.y + a1.y + a2.y + a3.y,
                           a0.z + a1.z + a2.z + a3.z,
                           a0.w + a1.w + a2.w + a3.w);
    float* dst = teacher ? g_tp : g_sp;
    *reinterpret_cast<float4*>(&dst[i4 * 4]) = r;
}

// ---------------------------------------------------------------------------
// U/V projections -> TRANSPOSED outputs [h][row]. (R4 champion, verbatim.)
// grid (16 rowblocks of 32, 4 mats), 256 thr. Micro 4r x 4c.
// ---------------------------------------------------------------------------
__global__ void __launch_bounds__(256)
uv_gemm(const float* __restrict__ W1, const float* __restrict__ b1) {
    const int XP = 36;
    const int WP = 132;
    __shared__ __align__(16) float Xst[HD * XP];
    __shared__ __align__(16) float Wsm[32 * WP];

    int which = blockIdx.y;
    const float* X = (which < 2) ? g_tp : g_sp;
    const float* W = W1 + ((which & 1) ? HD * HD : 0);
    float* outT = (which == 0) ? g_UtT : (which == 1) ? g_VtT
                : (which == 2) ? g_UsT : g_VsT;
    bool add_bias = ((which & 1) == 0);

    int tid = threadIdx.x;       // 256
    int rowsel = tid & 7;        // rows rowsel*4..+3
    int colsel = tid >> 3;       // cols colsel*4..+3
    int r0 = blockIdx.x * 32;

#pragma unroll
    for (int t = 0; t < 4; t++) {
        int i4 = tid + t * 256;
        int r = i4 >> 5, k4 = (i4 & 31) * 4;
        float4 v = *reinterpret_cast<const float4*>(&X[(r0 + r) * HD + k4]);
        Xst[(k4 + 0) * XP + r] = v.x;
        Xst[(k4 + 1) * XP + r] = v.y;
        Xst[(k4 + 2) * XP + r] = v.z;
        Xst[(k4 + 3) * XP + r] = v.w;
    }

    ull acc[4][2];   // [col][rowpair]
#pragma unroll
    for (int c = 0; c < 4; c++) { acc[c][0] = 0ull; acc[c][1] = 0ull; }

    for (int kc = 0; kc < HD; kc += 32) {
        __syncthreads();
#pragma unroll
        for (int t = 0; t < 4; t++) {
            int i4 = tid + t * 256;
            int kk = i4 >> 5, c4 = (i4 & 31) * 4;
            float4 v = *reinterpret_cast<const float4*>(&W[(kc + kk) * HD + c4]);
            *reinterpret_cast<float4*>(&Wsm[kk * WP + c4]) = v;
        }
        __syncthreads();
#pragma unroll 8
        for (int kk = 0; kk < 32; kk++) {
            int k = kc + kk;
            float2 a01 = *reinterpret_cast<const float2*>(&Xst[k * XP + rowsel * 4]);
            float2 a23 = *reinterpret_cast<const float2*>(&Xst[k * XP + rowsel * 4 + 2]);
            float4 w4 = *reinterpret_cast<const float4*>(&Wsm[kk * WP + colsel * 4]);
            ull ap0 = pk2(a01.x, a01.y), ap1 = pk2(a23.x, a23.y);
            ull w0 = pk2(w4.x, w4.x), w1 = pk2(w4.y, w4.y);
            ull w2d = pk2(w4.z, w4.z), w3 = pk2(w4.w, w4.w);
            fma2(acc[0][0], ap0, w0); fma2(acc[0][1], ap1, w0);
            fma2(acc[1][0], ap0, w1); fma2(acc[1][1], ap1, w1);
            fma2(acc[2][0], ap0, w2d); fma2(acc[2][1], ap1, w2d);
            fma2(acc[3][0], ap0, w3); fma2(acc[3][1], ap1, w3);
        }
    }

#pragma unroll
    for (int c = 0; c < 4; c++) {
        int col = colsel * 4 + c;
        float bias = add_bias ? b1[col] : 0.0f;
        float2 v0 = unpk2(acc[c][0]);
        float2 v1 = unpk2(acc[c][1]);
        float4 r = make_float4(v0.x + bias, v0.y + bias,
                               v1.x + bias, v1.y + bias);
        *reinterpret_cast<float4*>(&outT[col * BN + r0 + rowsel * 4]) = r;
    }
}

// ---------------------------------------------------------------------------
// Pairwise partial dots + distributed finalize.
// zz = net*4 + hsplit (HC=32). Tile 32(i) x 64(j), grid (8,16,8), 128 thr,
// micro 4i x 4j with rfma2 (R4 champion inner). After storing its partials,
// each block bumps the tile counter; the 8th arrival reduces the tile
// (sum partials -> sigmoid -> MSE) inline from L2 and atomicAdds into out.
// ---------------------------------------------------------------------------
__global__ void __launch_bounds__(128)
pairwise_part(const float* __restrict__ w2, const float* __restrict__ b2v,
              float* __restrict__ out) {
    const int HC = 32;
    const int US = 36;
    const int VS = 68;
    __shared__ __align__(16) float sU[HC * US];   // [h][i-row]
    __shared__ __align__(16) float sV[HC * VS];   // [h][j-row]
    __shared__ __align__(8)  float2 swd[HC];
    __shared__ unsigned int s_rank;
    __shared__ float sred[128];

    int zz = blockIdx.z;
    int net = zz >> 2;
    int hc = (zz & 3) * HC;
    const float* UT = net ? g_UsT : g_UtT;
    const float* VT = net ? g_VsT : g_VtT;
    float* pd = g_pd[zz];

    int tid = threadIdx.x;       // 128
    int tx = tid & 15;           // j = jbase + tx*4 + n
    int ty = tid >> 4;           // i = ibase + ty*4 + m
    int jbase = blockIdx.x * 64;
    int ibase = blockIdx.y * 32;

    // stage U tile: [h][r] (coalesced LDG, conflict-free STS)
#pragma unroll
    for (int t = 0; t < 8; t++) {
        int i = tid + t * 128;            // 1024: h = i>>5, r = i&31
        int h = i >> 5, r = i & 31;
        sU[h * US + r] = UT[(hc + h) * BN + ibase + r];
    }
#pragma unroll
    for (int t = 0; t < 16; t++) {
        int i = tid + t * 128;            // 2048: h = i>>6, r = i&63
        int h = i >> 6, r = i & 63;
        sV[h * VS + r] = VT[(hc + h) * BN + jbase + r];
    }
    if (tid < HC) { float w = w2[hc + tid]; swd[tid] = make_float2(w, w); }
    __syncthreads();

    ull acc[4][2];               // [n][i-pair]
#pragma unroll
    for (int n = 0; n < 4; n++) { acc[n][0] = 0ull; acc[n][1] = 0ull; }

#pragma unroll 8
    for (int h = 0; h < HC; h++) {
        ulonglong2 up = *reinterpret_cast<const ulonglong2*>(&sU[h * US + ty * 4]);
        float4 v4 = *reinterpret_cast<const float4*>(&sV[h * VS + tx * 4]);
        ull wd = *reinterpret_cast<const ull*>(&swd[h]);
        ull vd0 = pk2(v4.x, v4.x);
        ull vd1 = pk2(v4.y, v4.y);
        ull vd2 = pk2(v4.z, v4.z);
        ull vd3 = pk2(v4.w, v4.w);
        rfma2(acc[0][0], up.x, vd0, wd); rfma2(acc[0][1], up.y, vd0, wd);
        rfma2(acc[1][0], up.x, vd1, wd); rfma2(acc[1][1], up.y, vd1, wd);
        rfma2(acc[2][0], up.x, vd2, wd); rfma2(acc[2][1], up.y, vd2, wd);
        rfma2(acc[3][0], up.x, vd3, wd); rfma2(acc[3][1], up.y, vd3, wd);
    }

    float sums[4][4];            // [m][n]
#pragma unroll
    for (int n = 0; n < 4; n++) {
#pragma unroll
        for (int p = 0; p < 2; p++) {
            float2 v = unpk2(acc[n][p]);
            sums[p * 2 + 0][n] = v.x;
            sums[p * 2 + 1][n] = v.y;
        }
    }
#pragma unroll
    for (int m = 0; m < 4; m++) {
        int i = ibase + ty * 4 + m;
        *reinterpret_cast<float4*>(&pd[i * BN + jbase + tx * 4]) =
            make_float4(sums[m][0], sums[m][1], sums[m][2], sums[m][3]);
    }

    // ---- distributed finalize: 8th block for this tile reduces it ----
    __threadfence();
    if (tid == 0)
        s_rank = atomicAdd(&g_cnt[blockIdx.y * 8 + blockIdx.x], 1u);
    __syncthreads();
    if (s_rank != 7) return;

    float b2 = b2v[0];
    float local = 0.0f;
#pragma unroll
    for (int t = 0; t < 4; t++) {
        int gq = tid + t * 128;          // 512 groups of 4 cells
        int row = gq >> 4;               // 0..31
        int jl = (gq & 15) * 4;
        int base = (ibase + row) * BN + jbase + jl;
        float4 t0 = __ldcg(reinterpret_cast<const float4*>(&g_pd[0][base]));
        float4 t1 = __ldcg(reinterpret_cast<const float4*>(&g_pd[1][base]));
        float4 t2 = __ldcg(reinterpret_cast<const float4*>(&g_pd[2][base]));
        float4 t3 = __ldcg(reinterpret_cast<const float4*>(&g_pd[3][base]));
        float4 s0 = __ldcg(reinterpret_cast<const float4*>(&g_pd[4][base]));
        float4 s1 = __ldcg(reinterpret_cast<const float4*>(&g_pd[5][base]));
        float4 s2 = __ldcg(reinterpret_cast<const float4*>(&g_pd[6][base]));
        float4 s3 = __ldcg(reinterpret_cast<const float4*>(&g_pd[7][base]));
        float tv[4] = {(t0.x + t1.x) + (t2.x + t3.x),
                       (t0.y + t1.y) + (t2.y + t3.y),
                       (t0.z + t1.z) + (t2.z + t3.z),
                       (t0.w + t1.w) + (t2.w + t3.w)};
        float sv[4] = {(s0.x + s1.x) + (s2.x + s3.x),
                       (s0.y + s1.y) + (s2.y + s3.y),
                       (s0.z + s1.z) + (s2.z + s3.z),
                       (s0.w + s1.w) + (s2.w + s3.w)};
        int i = ibase + row;
#pragma unroll
        for (int n = 0; n < 4; n++) {
            if (i == jbase + jl + n) continue;   // diagonal: rel == 0 in both
            float rt = 1.0f / (1.0f + __expf(-(tv[n] + b2)));
            float rs = 1.0f / (1.0f + __expf(-(sv[n] + b2)));
            float d = rs - rt;
            local = fmaf(d, d, local);
        }
    }
    sred[tid] = local;
    __syncthreads();
    for (int st = 64; st > 0; st >>= 1) {
        if (tid < st) sred[tid] += sred[tid + st];
        __syncthreads();
    }
    if (tid == 0)
        atomicAdd(out, sred[0] * (1.0f / ((float)BN * (float)BN)));
}

// ---------------------------------------------------------------------------
extern "C" void kernel_launch(void* const* d_in, const int* in_sizes, int n_in,
                              void* d_out, int out_size) {
    const float* teacher = (const float*)d_in[0];
    const float* student = (const float*)d_in[1];
    const float* Wt = (const float*)d_in[2];
    const float* bt = (const float*)d_in[3];
    const float* Wsw = (const float*)d_in[4];
    const float* bs = (const float*)d_in[5];
    const float* W1 = (const float*)d_in[6];
    const float* b1 = (const float*)d_in[7];
    const float* W2 = (const float*)d_in[8];
    const float* b2 = (const float*)d_in[9];
    float* out = (float*)d_out;

    proj_gemm<<<dim3(16, 32, 2), 128>>>(teacher, Wt, student, Wsw);
    sumtp<<<128, 256>>>(bt, bs, out, out_size);
    uv_gemm<<<dim3(16, 4), 256>>>(W1, b1);
    pairwise_part<<<dim3(8, 16, 8), 128>>>(W2, b2, out);
}

// round 16
// speedup vs baseline: 1.2955x; 1.1665x over previous
#include <cuda_runtime.h>
#include <math.h>

#define BN 512
#define TD 2048
#define SD 768
#define HD 128

typedef unsigned long long ull;

// Scratch (device globals — no allocations allowed)
__device__ float g_tpp[32 * BN * HD];   // teacher proj partials (KLEN=64)
__device__ float g_spp[12 * BN * HD];   // student proj partials
__device__ float g_tp[BN * HD];
__device__ float g_sp[BN * HD];
// Transposed U/V: [h][row]
__device__ float g_UtT[HD * BN];
__device__ float g_VtT[HD * BN];
__device__ float g_UsT[HD * BN];
__device__ float g_VsT[HD * BN];
// Partial pre-sigmoid dots: [net*4 + hsplit][BN*BN]  (8 MB)
__device__ float g_pd[8][BN * BN];

// ---- packed f32x2 helpers (sm_100+) --------------------------------------
__device__ __forceinline__ ull pk2(float a, float b) {
    ull r; asm("mov.b64 %0, {%1, %2};" : "=l"(r) : "f"(a), "f"(b)); return r;
}
__device__ __forceinline__ float2 unpk2(ull v) {
    float2 r; asm("mov.b64 {%0, %1}, %2;" : "=f"(r.x), "=f"(r.y) : "l"(v)); return r;
}
__device__ __forceinline__ void fma2(ull &acc, ull a, ull b) {
    asm("fma.rn.f32x2 %0, %1, %2, %0;" : "+l"(acc) : "l"(a), "l"(b));
}
// acc += relu(a + b) * w (packed 2xfp32) — R4-champion formulation.
__device__ __forceinline__ void rfma2(ull &acc, ull a, ull b, ull w) {
    asm("{\n\t"
        ".reg .b64 t;\n\t"
        ".reg .f32 tl, th;\n\t"
        "add.rn.f32x2 t, %1, %2;\n\t"
        "mov.b64 {tl, th}, t;\n\t"
        "max.f32 tl, tl, 0f00000000;\n\t"
        "max.f32 th, th, 0f00000000;\n\t"
        "mov.b64 t, {tl, th};\n\t"
        "fma.rn.f32x2 %0, t, %3, %0;\n\t"
        "}"
        : "+l"(acc) : "l"(a), "l"(b), "l"(w));
}

// ---------------------------------------------------------------------------
// Projection GEMM partials, low-register micro. z=0 teacher (32 k-splits),
// z=1 student (12). KLEN=64, KC=32. Tile 32 rows x 64 cols (bx = 16 row
// tiles x 2 col halves), 128 thr, micro 4r x 4c = 8 packed acc chains.
// __launch_bounds__(128, 8) -> <=64 regs -> 32 warps/SM.
// ---------------------------------------------------------------------------
__global__ void __launch_bounds__(128, 8)
proj_gemm(const float* __restrict__ T, const float* __restrict__ Wt,
          const float* __restrict__ S, const float* __restrict__ Ws) {
    const int KC = 32;
    const int XP = 36;
    const int WS = 68;
    __shared__ __align__(16) float Xst[KC * XP];      // [k][r] transposed
    __shared__ __align__(16) float Wsm[KC * WS];      // [kk][c], 64 cols

    int z = blockIdx.z;
    int ky = blockIdx.y;
    const float* X; const float* W; float* outp; int ldx;
    if (z == 0) { X = T; W = Wt; ldx = TD; outp = g_tpp + ky * (BN * HD); }
    else {
        if (ky >= 12) return;
        X = S; W = Ws; ldx = SD; outp = g_spp + ky * (BN * HD);
    }

    int tid = threadIdx.x;        // 128
    int tx = tid & 15;            // cols tx*4..+3 (within 64-col half)
    int ty = tid >> 4;            // rows ty*4..+3 (0..7)
    int row0 = (blockIdx.x >> 1) * 32;
    int c0 = (blockIdx.x & 1) * 64;
    int k0 = ky * 64;

    ull acc[4][2];                // [row m][colpair q]
#pragma unroll
    for (int m = 0; m < 4; m++) { acc[m][0] = 0ull; acc[m][1] = 0ull; }

#pragma unroll
    for (int kc = 0; kc < 64; kc += KC) {
        // stage X tile 32r x 32k transposed (256 f4, 2/thread)
#pragma unroll
        for (int t = 0; t < 2; t++) {
            int i4 = tid + t * 128;
            int r = i4 >> 3, k4 = (i4 & 7) * 4;
            float4 v = *reinterpret_cast<const float4*>(
                &X[(row0 + r) * ldx + k0 + kc + k4]);
            Xst[(k4 + 0) * XP + r] = v.x;
            Xst[(k4 + 1) * XP + r] = v.y;
            Xst[(k4 + 2) * XP + r] = v.z;
            Xst[(k4 + 3) * XP + r] = v.w;
        }
        // stage W tile 32k x 64c (512 f4, 4/thread)
#pragma unroll
        for (int t = 0; t < 4; t++) {
            int i4 = tid + t * 128;
            int kk = i4 >> 4, c4 = (i4 & 15) * 4;
            float4 v = *reinterpret_cast<const float4*>(
                &W[(k0 + kc + kk) * HD + c0 + c4]);
            *reinterpret_cast<float4*>(&Wsm[kk * WS + c4]) = v;
        }
        __syncthreads();
#pragma unroll 8
        for (int kk = 0; kk < KC; kk++) {
            float4 a4 = *reinterpret_cast<const float4*>(&Xst[kk * XP + ty * 4]);
            ulonglong2 bp = *reinterpret_cast<const ulonglong2*>(&Wsm[kk * WS + tx * 4]);
            ull a0 = pk2(a4.x, a4.x), a1 = pk2(a4.y, a4.y);
            ull a2 = pk2(a4.z, a4.z), a3 = pk2(a4.w, a4.w);
            fma2(acc[0][0], a0, bp.x); fma2(acc[0][1], a0, bp.y);
            fma2(acc[1][0], a1, bp.x); fma2(acc[1][1], a1, bp.y);
            fma2(acc[2][0], a2, bp.x); fma2(acc[2][1], a2, bp.y);
            fma2(acc[3][0], a3, bp.x); fma2(acc[3][1], a3, bp.y);
        }
        __syncthreads();
    }
#pragma unroll
    for (int m = 0; m < 4; m++) {
        int row = row0 + ty * 4 + m;
        float2 q0 = unpk2(acc[m][0]);
        float2 q1 = unpk2(acc[m][1]);
        *reinterpret_cast<float4*>(&outp[row * HD + c0 + tx * 4]) =
            make_float4(q0.x, q0.y, q1.x, q1.y);
    }
}

// ---------------------------------------------------------------------------
// Sum proj partials + bias -> g_tp / g_sp. Grid 128 x 256 thr.
// Also zeroes the output scalar (block 0). (R4 champion, verbatim.)
// ---------------------------------------------------------------------------
__global__ void __launch_bounds__(256)
sumtp(const float* __restrict__ bt, const float* __restrict__ bs,
      float* __restrict__ out, int out_size) {
    if (blockIdx.x == 0) {
        for (int i = threadIdx.x; i < out_size; i += 256) out[i] = 0.0f;
    }
    int b = blockIdx.x;
    int teacher = (b < 64);
    int i4 = (teacher ? b : b - 64) * 256 + threadIdx.x;
    int k4 = (i4 & 31) * 4;
    const float* bias = teacher ? bt : bs;
    const float* pbase = teacher ? g_tpp : g_spp;
    int np = teacher ? 32 : 12;

    float4 a0 = *reinterpret_cast<const float4*>(&bias[k4]);
    float4 a1 = make_float4(0.f, 0.f, 0.f, 0.f);
    float4 a2 = make_float4(0.f, 0.f, 0.f, 0.f);
    float4 a3 = make_float4(0.f, 0.f, 0.f, 0.f);
    for (int p = 0; p < np; p += 4) {
        float4 v0 = *reinterpret_cast<const float4*>(&pbase[(p + 0) * (BN * HD) + i4 * 4]);
        float4 v1 = *reinterpret_cast<const float4*>(&pbase[(p + 1) * (BN * HD) + i4 * 4]);
        float4 v2 = *reinterpret_cast<const float4*>(&pbase[(p + 2) * (BN * HD) + i4 * 4]);
        float4 v3 = *reinterpret_cast<const float4*>(&pbase[(p + 3) * (BN * HD) + i4 * 4]);
        a0.x += v0.x; a0.y += v0.y; a0.z += v0.z; a0.w += v0.w;
        a1.x += v1.x; a1.y += v1.y; a1.z += v1.z; a1.w += v1.w;
        a2.x += v2.x; a2.y += v2.y; a2.z += v2.z; a2.w += v2.w;
        a3.x += v3.x; a3.y += v3.y; a3.z += v3.z; a3.w += v3.w;
    }
    float4 r = make_float4(a0.x + a1.x + a2.x + a3.x,
                           a0.y + a1.y + a2.y + a3.y,
                           a0.z + a1.z + a2.z + a3.z,
                           a0.w + a1.w + a2.w + a3.w);
    float* dst = teacher ? g_tp : g_sp;
    *reinterpret_cast<float4*>(&dst[i4 * 4]) = r;
}

// ---------------------------------------------------------------------------
// U/V projections -> TRANSPOSED outputs [h][row]. (R4 champion, verbatim.)
// grid (16 rowblocks of 32, 4 mats), 256 thr. Micro 4r x 4c.
// ---------------------------------------------------------------------------
__global__ void __launch_bounds__(256)
uv_gemm(const float* __restrict__ W1, const float* __restrict__ b1) {
    const int XP = 36;
    const int WP = 132;
    __shared__ __align__(16) float Xst[HD * XP];
    __shared__ __align__(16) float Wsm[32 * WP];

    int which = blockIdx.y;
    const float* X = (which < 2) ? g_tp : g_sp;
    const float* W = W1 + ((which & 1) ? HD * HD : 0);
    float* outT = (which == 0) ? g_UtT : (which == 1) ? g_VtT
                : (which == 2) ? g_UsT : g_VsT;
    bool add_bias = ((which & 1) == 0);

    int tid = threadIdx.x;       // 256
    int rowsel = tid & 7;        // rows rowsel*4..+3
    int colsel = tid >> 3;       // cols colsel*4..+3
    int r0 = blockIdx.x * 32;

#pragma unroll
    for (int t = 0; t < 4; t++) {
        int i4 = tid + t * 256;
        int r = i4 >> 5, k4 = (i4 & 31) * 4;
        float4 v = *reinterpret_cast<const float4*>(&X[(r0 + r) * HD + k4]);
        Xst[(k4 + 0) * XP + r] = v.x;
        Xst[(k4 + 1) * XP + r] = v.y;
        Xst[(k4 + 2) * XP + r] = v.z;
        Xst[(k4 + 3) * XP + r] = v.w;
    }

    ull acc[4][2];   // [col][rowpair]
#pragma unroll
    for (int c = 0; c < 4; c++) { acc[c][0] = 0ull; acc[c][1] = 0ull; }

    for (int kc = 0; kc < HD; kc += 32) {
        __syncthreads();
#pragma unroll
        for (int t = 0; t < 4; t++) {
            int i4 = tid + t * 256;
            int kk = i4 >> 5, c4 = (i4 & 31) * 4;
            float4 v = *reinterpret_cast<const float4*>(&W[(kc + kk) * HD + c4]);
            *reinterpret_cast<float4*>(&Wsm[kk * WP + c4]) = v;
        }
        __syncthreads();
#pragma unroll 8
        for (int kk = 0; kk < 32; kk++) {
            int k = kc + kk;
            float2 a01 = *reinterpret_cast<const float2*>(&Xst[k * XP + rowsel * 4]);
            float2 a23 = *reinterpret_cast<const float2*>(&Xst[k * XP + rowsel * 4 + 2]);
            float4 w4 = *reinterpret_cast<const float4*>(&Wsm[kk * WP + colsel * 4]);
            ull ap0 = pk2(a01.x, a01.y), ap1 = pk2(a23.x, a23.y);
            ull w0 = pk2(w4.x, w4.x), w1 = pk2(w4.y, w4.y);
            ull w2d = pk2(w4.z, w4.z), w3 = pk2(w4.w, w4.w);
            fma2(acc[0][0], ap0, w0); fma2(acc[0][1], ap1, w0);
            fma2(acc[1][0], ap0, w1); fma2(acc[1][1], ap1, w1);
            fma2(acc[2][0], ap0, w2d); fma2(acc[2][1], ap1, w2d);
            fma2(acc[3][0], ap0, w3); fma2(acc[3][1], ap1, w3);
        }
    }

#pragma unroll
    for (int c = 0; c < 4; c++) {
        int col = colsel * 4 + c;
        float bias = add_bias ? b1[col] : 0.0f;
        float2 v0 = unpk2(acc[c][0]);
        float2 v1 = unpk2(acc[c][1]);
        float4 r = make_float4(v0.x + bias, v0.y + bias,
                               v1.x + bias, v1.y + bias);
        *reinterpret_cast<float4*>(&outT[col * BN + r0 + rowsel * 4]) = r;
    }
}

// ---------------------------------------------------------------------------
// Pairwise partial dots. (R4 champion 11.6us kernel, verbatim.)
// zz = net*4 + hsplit (HC=32). Tile 32(i) x 64(j), grid (8,16,8), 128 thr,
// micro 4i x 4j with rfma2; inputs transposed [h][row].
// ---------------------------------------------------------------------------
__global__ void __launch_bounds__(128)
pairwise_part(const float* __restrict__ w2) {
    const int HC = 32;
    const int US = 36;
    const int VS = 68;
    __shared__ __align__(16) float sU[HC * US];   // [h][i-row]
    __shared__ __align__(16) float sV[HC * VS];   // [h][j-row]
    __shared__ __align__(8)  float2 swd[HC];

    int zz = blockIdx.z;
    int net = zz >> 2;
    int hc = (zz & 3) * HC;
    const float* UT = net ? g_UsT : g_UtT;
    const float* VT = net ? g_VsT : g_VtT;
    float* pd = g_pd[zz];

    int tid = threadIdx.x;       // 128
    int tx = tid & 15;           // j = jbase + tx*4 + n
    int ty = tid >> 4;           // i = ibase + ty*4 + m
    int jbase = blockIdx.x * 64;
    int ibase = blockIdx.y * 32;

#pragma unroll
    for (int t = 0; t < 8; t++) {
        int i = tid + t * 128;            // 1024: h = i>>5, r = i&31
        int h = i >> 5, r = i & 31;
        sU[h * US + r] = UT[(hc + h) * BN + ibase + r];
    }
#pragma unroll
    for (int t = 0; t < 16; t++) {
        int i = tid + t * 128;            // 2048: h = i>>6, r = i&63
        int h = i >> 6, r = i & 63;
        sV[h * VS + r] = VT[(hc + h) * BN + jbase + r];
    }
    if (tid < HC) { float w = w2[hc + tid]; swd[tid] = make_float2(w, w); }
    __syncthreads();

    ull acc[4][2];               // [n][i-pair]
#pragma unroll
    for (int n = 0; n < 4; n++) { acc[n][0] = 0ull; acc[n][1] = 0ull; }

#pragma unroll 8
    for (int h = 0; h < HC; h++) {
        ulonglong2 up = *reinterpret_cast<const ulonglong2*>(&sU[h * US + ty * 4]);
        float4 v4 = *reinterpret_cast<const float4*>(&sV[h * VS + tx * 4]);
        ull wd = *reinterpret_cast<const ull*>(&swd[h]);
        ull vd0 = pk2(v4.x, v4.x);
        ull vd1 = pk2(v4.y, v4.y);
        ull vd2 = pk2(v4.z, v4.z);
        ull vd3 = pk2(v4.w, v4.w);
        rfma2(acc[0][0], up.x, vd0, wd); rfma2(acc[0][1], up.y, vd0, wd);
        rfma2(acc[1][0], up.x, vd1, wd); rfma2(acc[1][1], up.y, vd1, wd);
        rfma2(acc[2][0], up.x, vd2, wd); rfma2(acc[2][1], up.y, vd2, wd);
        rfma2(acc[3][0], up.x, vd3, wd); rfma2(acc[3][1], up.y, vd3, wd);
    }

    float sums[4][4];            // [m][n]
#pragma unroll
    for (int n = 0; n < 4; n++) {
#pragma unroll
        for (int p = 0; p < 2; p++) {
            float2 v = unpk2(acc[n][p]);
            sums[p * 2 + 0][n] = v.x;
            sums[p * 2 + 1][n] = v.y;
        }
    }
#pragma unroll
    for (int m = 0; m < 4; m++) {
        int i = ibase + ty * 4 + m;
        *reinterpret_cast<float4*>(&pd[i * BN + jbase + tx * 4]) =
            make_float4(sums[m][0], sums[m][1], sums[m][2], sums[m][3]);
    }
}

// ---------------------------------------------------------------------------
// Reduce: rel = sigmoid(sum of 4 h-partials + b2) per net, diag skipped,
// MSE atomically accumulated into out. 512 blocks x 128 thr, front-batched
// MLP-8 loads, warp-shuffle reduction (no sync tree).
// ---------------------------------------------------------------------------
__global__ void __launch_bounds__(128)
reduce_kernel(const float* __restrict__ b2v, float* __restrict__ out) {
    __shared__ float swarp[4];
    int g = blockIdx.x * 128 + threadIdx.x;     // 65536 groups of 4
    int i = g >> 7;
    int j0 = (g & 127) * 4;
    float b2 = b2v[0];

    float4 t0 = *reinterpret_cast<const float4*>(&g_pd[0][g * 4]);
    float4 t1 = *reinterpret_cast<const float4*>(&g_pd[1][g * 4]);
    float4 t2 = *reinterpret_cast<const float4*>(&g_pd[2][g * 4]);
    float4 t3 = *reinterpret_cast<const float4*>(&g_pd[3][g * 4]);
    float4 s0 = *reinterpret_cast<const float4*>(&g_pd[4][g * 4]);
    float4 s1 = *reinterpret_cast<const float4*>(&g_pd[5][g * 4]);
    float4 s2 = *reinterpret_cast<const float4*>(&g_pd[6][g * 4]);
    float4 s3 = *reinterpret_cast<const float4*>(&g_pd[7][g * 4]);

    float tv[4] = {(t0.x + t1.x) + (t2.x + t3.x),
                   (t0.y + t1.y) + (t2.y + t3.y),
                   (t0.z + t1.z) + (t2.z + t3.z),
                   (t0.w + t1.w) + (t2.w + t3.w)};
    float sv[4] = {(s0.x + s1.x) + (s2.x + s3.x),
                   (s0.y + s1.y) + (s2.y + s3.y),
                   (s0.z + s1.z) + (s2.z + s3.z),
                   (s0.w + s1.w) + (s2.w + s3.w)};
    float local = 0.0f;
#pragma unroll
    for (int n = 0; n < 4; n++) {
        if (i == j0 + n) continue;   // diagonal: rel defined 0 in both
        float rt = 1.0f / (1.0f + __expf(-(tv[n] + b2)));
        float rs = 1.0f / (1.0f + __expf(-(sv[n] + b2)));
        float d = rs - rt;
        local = fmaf(d, d, local);
    }

    // warp-level reduction
#pragma unroll
    for (int off = 16; off > 0; off >>= 1)
        local += __shfl_down_sync(0xFFFFFFFFu, local, off);
    int lane = threadIdx.x & 31;
    int wid = threadIdx.x >> 5;
    if (lane == 0) swarp[wid] = local;
    __syncthreads();
    if (threadIdx.x == 0) {
        float s = swarp[0] + swarp[1] + swarp[2] + swarp[3];
        atomicAdd(out, s * (1.0f / ((float)BN * (float)BN)));
    }
}

// ---------------------------------------------------------------------------
extern "C" void kernel_launch(void* const* d_in, const int* in_sizes, int n_in,
                              void* d_out, int out_size) {
    const float* teacher = (const float*)d_in[0];
    const float* student = (const float*)d_in[1];
    const float* Wt = (const float*)d_in[2];
    const float* bt = (const float*)d_in[3];
    const float* Wsw = (const float*)d_in[4];
    const float* bs = (const float*)d_in[5];
    const float* W1 = (const float*)d_in[6];
    const float* b1 = (const float*)d_in[7];
    const float* W2 = (const float*)d_in[8];
    const float* b2 = (const float*)d_in[9];
    float* out = (float*)d_out;

    proj_gemm<<<dim3(32, 32, 2), 128>>>(teacher, Wt, student, Wsw);
    sumtp<<<128, 256>>>(bt, bs, out, out_size);
    uv_gemm<<<dim3(16, 4), 256>>>(W1, b1);
    pairwise_part<<<dim3(8, 16, 8), 128>>>(W2);
    reduce_kernel<<<512, 128>>>(b2, out);
}

// round 17
// speedup vs baseline: 1.3591x; 1.0491x over previous
#include <cuda_runtime.h>
#include <math.h>

#define BN 512
#define TD 2048
#define SD 768
#define HD 128

typedef unsigned long long ull;

// Scratch (device globals — no allocations allowed)
__device__ float g_tpp[32 * BN * HD];   // teacher proj partials (KLEN=64)
__device__ float g_spp[12 * BN * HD];   // student proj partials
__device__ float g_tp[BN * HD];
__device__ float g_sp[BN * HD];
// Transposed U/V: [h][row]
__device__ float g_UtT[HD * BN];
__device__ float g_VtT[HD * BN];
__device__ float g_UsT[HD * BN];
__device__ float g_VsT[HD * BN];
// Partial pre-sigmoid dots: [net*8 + hsplit][BN*BN]  (16 MB)
__device__ float g_pd[16][BN * BN];

// ---- packed f32x2 helpers (sm_100+) --------------------------------------
__device__ __forceinline__ ull pk2(float a, float b) {
    ull r; asm("mov.b64 %0, {%1, %2};" : "=l"(r) : "f"(a), "f"(b)); return r;
}
__device__ __forceinline__ float2 unpk2(ull v) {
    float2 r; asm("mov.b64 {%0, %1}, %2;" : "=f"(r.x), "=f"(r.y) : "l"(v)); return r;
}
__device__ __forceinline__ void fma2(ull &acc, ull a, ull b) {
    asm("fma.rn.f32x2 %0, %1, %2, %0;" : "+l"(acc) : "l"(a), "l"(b));
}
// acc += relu(a + b) * w (packed 2xfp32) — R4-champion formulation.
__device__ __forceinline__ void rfma2(ull &acc, ull a, ull b, ull w) {
    asm("{\n\t"
        ".reg .b64 t;\n\t"
        ".reg .f32 tl, th;\n\t"
        "add.rn.f32x2 t, %1, %2;\n\t"
        "mov.b64 {tl, th}, t;\n\t"
        "max.f32 tl, tl, 0f00000000;\n\t"
        "max.f32 th, th, 0f00000000;\n\t"
        "mov.b64 t, {tl, th};\n\t"
        "fma.rn.f32x2 %0, t, %3, %0;\n\t"
        "}"
        : "+l"(acc) : "l"(a), "l"(b), "l"(w));
}

// ---------------------------------------------------------------------------
// Projection GEMM partials, low-register micro. (R16 champion, verbatim.)
// z=0 teacher (32 k-splits), z=1 student (12). KLEN=64, KC=32.
// Tile 32 rows x 64 cols (bx = 16 row tiles x 2 col halves), 128 thr,
// micro 4r x 4c. __launch_bounds__(128, 8) -> 32 warps/SM.
// ---------------------------------------------------------------------------
__global__ void __launch_bounds__(128, 8)
proj_gemm(const float* __restrict__ T, const float* __restrict__ Wt,
          const float* __restrict__ S, const float* __restrict__ Ws) {
    const int KC = 32;
    const int XP = 36;
    const int WS = 68;
    __shared__ __align__(16) float Xst[KC * XP];      // [k][r] transposed
    __shared__ __align__(16) float Wsm[KC * WS];      // [kk][c], 64 cols

    int z = blockIdx.z;
    int ky = blockIdx.y;
    const float* X; const float* W; float* outp; int ldx;
    if (z == 0) { X = T; W = Wt; ldx = TD; outp = g_tpp + ky * (BN * HD); }
    else {
        if (ky >= 12) return;
        X = S; W = Ws; ldx = SD; outp = g_spp + ky * (BN * HD);
    }

    int tid = threadIdx.x;        // 128
    int tx = tid & 15;            // cols tx*4..+3 (within 64-col half)
    int ty = tid >> 4;            // rows ty*4..+3 (0..7)
    int row0 = (blockIdx.x >> 1) * 32;
    int c0 = (blockIdx.x & 1) * 64;
    int k0 = ky * 64;

    ull acc[4][2];                // [row m][colpair q]
#pragma unroll
    for (int m = 0; m < 4; m++) { acc[m][0] = 0ull; acc[m][1] = 0ull; }

#pragma unroll
    for (int kc = 0; kc < 64; kc += KC) {
#pragma unroll
        for (int t = 0; t < 2; t++) {
            int i4 = tid + t * 128;
            int r = i4 >> 3, k4 = (i4 & 7) * 4;
            float4 v = *reinterpret_cast<const float4*>(
                &X[(row0 + r) * ldx + k0 + kc + k4]);
            Xst[(k4 + 0) * XP + r] = v.x;
            Xst[(k4 + 1) * XP + r] = v.y;
            Xst[(k4 + 2) * XP + r] = v.z;
            Xst[(k4 + 3) * XP + r] = v.w;
        }
#pragma unroll
        for (int t = 0; t < 4; t++) {
            int i4 = tid + t * 128;
            int kk = i4 >> 4, c4 = (i4 & 15) * 4;
            float4 v = *reinterpret_cast<const float4*>(
                &W[(k0 + kc + kk) * HD + c0 + c4]);
            *reinterpret_cast<float4*>(&Wsm[kk * WS + c4]) = v;
        }
        __syncthreads();
#pragma unroll 8
        for (int kk = 0; kk < KC; kk++) {
            float4 a4 = *reinterpret_cast<const float4*>(&Xst[kk * XP + ty * 4]);
            ulonglong2 bp = *reinterpret_cast<const ulonglong2*>(&Wsm[kk * WS + tx * 4]);
            ull a0 = pk2(a4.x, a4.x), a1 = pk2(a4.y, a4.y);
            ull a2 = pk2(a4.z, a4.z), a3 = pk2(a4.w, a4.w);
            fma2(acc[0][0], a0, bp.x); fma2(acc[0][1], a0, bp.y);
            fma2(acc[1][0], a1, bp.x); fma2(acc[1][1], a1, bp.y);
            fma2(acc[2][0], a2, bp.x); fma2(acc[2][1], a2, bp.y);
            fma2(acc[3][0], a3, bp.x); fma2(acc[3][1], a3, bp.y);
        }
        __syncthreads();
    }
#pragma unroll
    for (int m = 0; m < 4; m++) {
        int row = row0 + ty * 4 + m;
        float2 q0 = unpk2(acc[m][0]);
        float2 q1 = unpk2(acc[m][1]);
        *reinterpret_cast<float4*>(&outp[row * HD + c0 + tx * 4]) =
            make_float4(q0.x, q0.y, q1.x, q1.y);
    }
}

// ---------------------------------------------------------------------------
// Sum proj partials + bias -> g_tp / g_sp. Grid 128 x 256 thr.
// Also zeroes the output scalar (block 0). (Champion, verbatim.)
// ---------------------------------------------------------------------------
__global__ void __launch_bounds__(256)
sumtp(const float* __restrict__ bt, const float* __restrict__ bs,
      float* __restrict__ out, int out_size) {
    if (blockIdx.x == 0) {
        for (int i = threadIdx.x; i < out_size; i += 256) out[i] = 0.0f;
    }
    int b = blockIdx.x;
    int teacher = (b < 64);
    int i4 = (teacher ? b : b - 64) * 256 + threadIdx.x;
    int k4 = (i4 & 31) * 4;
    const float* bias = teacher ? bt : bs;
    const float* pbase = teacher ? g_tpp : g_spp;
    int np = teacher ? 32 : 12;

    float4 a0 = *reinterpret_cast<const float4*>(&bias[k4]);
    float4 a1 = make_float4(0.f, 0.f, 0.f, 0.f);
    float4 a2 = make_float4(0.f, 0.f, 0.f, 0.f);
    float4 a3 = make_float4(0.f, 0.f, 0.f, 0.f);
    for (int p = 0; p < np; p += 4) {
        float4 v0 = *reinterpret_cast<const float4*>(&pbase[(p + 0) * (BN * HD) + i4 * 4]);
        float4 v1 = *reinterpret_cast<const float4*>(&pbase[(p + 1) * (BN * HD) + i4 * 4]);
        float4 v2 = *reinterpret_cast<const float4*>(&pbase[(p + 2) * (BN * HD) + i4 * 4]);
        float4 v3 = *reinterpret_cast<const float4*>(&pbase[(p + 3) * (BN * HD) + i4 * 4]);
        a0.x += v0.x; a0.y += v0.y; a0.z += v0.z; a0.w += v0.w;
        a1.x += v1.x; a1.y += v1.y; a1.z += v1.z; a1.w += v1.w;
        a2.x += v2.x; a2.y += v2.y; a2.z += v2.z; a2.w += v2.w;
        a3.x += v3.x; a3.y += v3.y; a3.z += v3.z; a3.w += v3.w;
    }
    float4 r = make_float4(a0.x + a1.x + a2.x + a3.x,
                           a0.y + a1.y + a2.y + a3.y,
                           a0.z + a1.z + a2.z + a3.z,
                           a0.w + a1.w + a2.w + a3.w);
    float* dst = teacher ? g_tp : g_sp;
    *reinterpret_cast<float4*>(&dst[i4 * 4]) = r;
}

// ---------------------------------------------------------------------------
// U/V projections -> TRANSPOSED outputs [h][row]. (Champion, verbatim.)
// grid (16 rowblocks of 32, 4 mats), 256 thr. Micro 4r x 4c.
// ---------------------------------------------------------------------------
__global__ void __launch_bounds__(256)
uv_gemm(const float* __restrict__ W1, const float* __restrict__ b1) {
    const int XP = 36;
    const int WP = 132;
    __shared__ __align__(16) float Xst[HD * XP];
    __shared__ __align__(16) float Wsm[32 * WP];

    int which = blockIdx.y;
    const float* X = (which < 2) ? g_tp : g_sp;
    const float* W = W1 + ((which & 1) ? HD * HD : 0);
    float* outT = (which == 0) ? g_UtT : (which == 1) ? g_VtT
                : (which == 2) ? g_UsT : g_VsT;
    bool add_bias = ((which & 1) == 0);

    int tid = threadIdx.x;       // 256
    int rowsel = tid & 7;        // rows rowsel*4..+3
    int colsel = tid >> 3;       // cols colsel*4..+3
    int r0 = blockIdx.x * 32;

#pragma unroll
    for (int t = 0; t < 4; t++) {
        int i4 = tid + t * 256;
        int r = i4 >> 5, k4 = (i4 & 31) * 4;
        float4 v = *reinterpret_cast<const float4*>(&X[(r0 + r) * HD + k4]);
        Xst[(k4 + 0) * XP + r] = v.x;
        Xst[(k4 + 1) * XP + r] = v.y;
        Xst[(k4 + 2) * XP + r] = v.z;
        Xst[(k4 + 3) * XP + r] = v.w;
    }

    ull acc[4][2];   // [col][rowpair]
#pragma unroll
    for (int c = 0; c < 4; c++) { acc[c][0] = 0ull; acc[c][1] = 0ull; }

    for (int kc = 0; kc < HD; kc += 32) {
        __syncthreads();
#pragma unroll
        for (int t = 0; t < 4; t++) {
            int i4 = tid + t * 256;
            int kk = i4 >> 5, c4 = (i4 & 31) * 4;
            float4 v = *reinterpret_cast<const float4*>(&W[(kc + kk) * HD + c4]);
            *reinterpret_cast<float4*>(&Wsm[kk * WP + c4]) = v;
        }
        __syncthreads();
#pragma unroll 8
        for (int kk = 0; kk < 32; kk++) {
            int k = kc + kk;
            float2 a01 = *reinterpret_cast<const float2*>(&Xst[k * XP + rowsel * 4]);
            float2 a23 = *reinterpret_cast<const float2*>(&Xst[k * XP + rowsel * 4 + 2]);
            float4 w4 = *reinterpret_cast<const float4*>(&Wsm[kk * WP + colsel * 4]);
            ull ap0 = pk2(a01.x, a01.y), ap1 = pk2(a23.x, a23.y);
            ull w0 = pk2(w4.x, w4.x), w1 = pk2(w4.y, w4.y);
            ull w2d = pk2(w4.z, w4.z), w3 = pk2(w4.w, w4.w);
            fma2(acc[0][0], ap0, w0); fma2(acc[0][1], ap1, w0);
            fma2(acc[1][0], ap0, w1); fma2(acc[1][1], ap1, w1);
            fma2(acc[2][0], ap0, w2d); fma2(acc[2][1], ap1, w2d);
            fma2(acc[3][0], ap0, w3); fma2(acc[3][1], ap1, w3);
        }
    }

#pragma unroll
    for (int c = 0; c < 4; c++) {
        int col = colsel * 4 + c;
        float bias = add_bias ? b1[col] : 0.0f;
        float2 v0 = unpk2(acc[c][0]);
        float2 v1 = unpk2(acc[c][1]);
        float4 r = make_float4(v0.x + bias, v0.y + bias,
                               v1.x + bias, v1.y + bias);
        *reinterpret_cast<float4*>(&outT[col * BN + r0 + rowsel * 4]) = r;
    }
}

// ---------------------------------------------------------------------------
// Pairwise partial dots, h-split x8. zz = net*8 + hsplit (HC=16).
// Tile 32(i) x 64(j), grid (8,16,16) = 2048 blocks, 128 thr,
// micro 4i x 4j with rfma2 (champion inner, byte-identical per position).
// ---------------------------------------------------------------------------
__global__ void __launch_bounds__(128)
pairwise_part(const float* __restrict__ w2) {
    const int HC = 16;
    const int US = 36;
    const int VS = 68;
    __shared__ __align__(16) float sU[HC * US];   // [h][i-row]
    __shared__ __align__(16) float sV[HC * VS];   // [h][j-row]
    __shared__ __align__(8)  float2 swd[HC];

    int zz = blockIdx.z;          // 0..15
    int net = zz >> 3;
    int hc = (zz & 7) * HC;
    const float* UT = net ? g_UsT : g_UtT;
    const float* VT = net ? g_VsT : g_VtT;
    float* pd = g_pd[zz];

    int tid = threadIdx.x;       // 128
    int tx = tid & 15;           // j = jbase + tx*4 + n
    int ty = tid >> 4;           // i = ibase + ty*4 + m
    int jbase = blockIdx.x * 64;
    int ibase = blockIdx.y * 32;

    // stage U tile: [h][r] (coalesced LDG, conflict-free STS)
#pragma unroll
    for (int t = 0; t < 4; t++) {
        int i = tid + t * 128;            // 512: h = i>>5, r = i&31
        int h = i >> 5, r = i & 31;
        sU[h * US + r] = UT[(hc + h) * BN + ibase + r];
    }
#pragma unroll
    for (int t = 0; t < 8; t++) {
        int i = tid + t * 128;            // 1024: h = i>>6, r = i&63
        int h = i >> 6, r = i & 63;
        sV[h * VS + r] = VT[(hc + h) * BN + jbase + r];
    }
    if (tid < HC) { float w = w2[hc + tid]; swd[tid] = make_float2(w, w); }
    __syncthreads();

    ull acc[4][2];               // [n][i-pair]
#pragma unroll
    for (int n = 0; n < 4; n++) { acc[n][0] = 0ull; acc[n][1] = 0ull; }

#pragma unroll
    for (int h = 0; h < HC; h++) {
        ulonglong2 up = *reinterpret_cast<const ulonglong2*>(&sU[h * US + ty * 4]);
        float4 v4 = *reinterpret_cast<const float4*>(&sV[h * VS + tx * 4]);
        ull wd = *reinterpret_cast<const ull*>(&swd[h]);
        ull vd0 = pk2(v4.x, v4.x);
        ull vd1 = pk2(v4.y, v4.y);
        ull vd2 = pk2(v4.z, v4.z);
        ull vd3 = pk2(v4.w, v4.w);
        rfma2(acc[0][0], up.x, vd0, wd); rfma2(acc[0][1], up.y, vd0, wd);
        rfma2(acc[1][0], up.x, vd1, wd); rfma2(acc[1][1], up.y, vd1, wd);
        rfma2(acc[2][0], up.x, vd2, wd); rfma2(acc[2][1], up.y, vd2, wd);
        rfma2(acc[3][0], up.x, vd3, wd); rfma2(acc[3][1], up.y, vd3, wd);
    }

    float sums[4][4];            // [m][n]
#pragma unroll
    for (int n = 0; n < 4; n++) {
#pragma unroll
        for (int p = 0; p < 2; p++) {
            float2 v = unpk2(acc[n][p]);
            sums[p * 2 + 0][n] = v.x;
            sums[p * 2 + 1][n] = v.y;
        }
    }
#pragma unroll
    for (int m = 0; m < 4; m++) {
        int i = ibase + ty * 4 + m;
        *reinterpret_cast<float4*>(&pd[i * BN + jbase + tx * 4]) =
            make_float4(sums[m][0], sums[m][1], sums[m][2], sums[m][3]);
    }
}

// ---------------------------------------------------------------------------
// Reduce: rel = sigmoid(sum of 8 h-partials + b2) per net, diag skipped,
// MSE atomically accumulated into out. 512 blocks x 128 thr, front-batched
// MLP-16 loads, warp-shuffle reduction.
// ---------------------------------------------------------------------------
__global__ void __launch_bounds__(128)
reduce_kernel(const float* __restrict__ b2v, float* __restrict__ out) {
    __shared__ float swarp[4];
    int g = blockIdx.x * 128 + threadIdx.x;     // 65536 groups of 4
    int i = g >> 7;
    int j0 = (g & 127) * 4;
    float b2 = b2v[0];

    float4 t[8], s[8];
#pragma unroll
    for (int k = 0; k < 8; k++)
        t[k] = *reinterpret_cast<const float4*>(&g_pd[k][g * 4]);
#pragma unroll
    for (int k = 0; k < 8; k++)
        s[k] = *reinterpret_cast<const float4*>(&g_pd[8 + k][g * 4]);

    float tv[4], sv[4];
#pragma unroll
    for (int c = 0; c < 4; c++) {
        float* tp = reinterpret_cast<float*>(t);
        float* sp = reinterpret_cast<float*>(s);
        float ta = ((tp[0*4+c] + tp[1*4+c]) + (tp[2*4+c] + tp[3*4+c]))
                 + ((tp[4*4+c] + tp[5*4+c]) + (tp[6*4+c] + tp[7*4+c]));
        float sa = ((sp[0*4+c] + sp[1*4+c]) + (sp[2*4+c] + sp[3*4+c]))
                 + ((sp[4*4+c] + sp[5*4+c]) + (sp[6*4+c] + sp[7*4+c]));
        tv[c] = ta; sv[c] = sa;
    }

    float local = 0.0f;
#pragma unroll
    for (int n = 0; n < 4; n++) {
        if (i == j0 + n) continue;   // diagonal: rel defined 0 in both
        float rt = 1.0f / (1.0f + __expf(-(tv[n] + b2)));
        float rs = 1.0f / (1.0f + __expf(-(sv[n] + b2)));
        float d = rs - rt;
        local = fmaf(d, d, local);
    }

#pragma unroll
    for (int off = 16; off > 0; off >>= 1)
        local += __shfl_down_sync(0xFFFFFFFFu, local, off);
    int lane = threadIdx.x & 31;
    int wid = threadIdx.x >> 5;
    if (lane == 0) swarp[wid] = local;
    __syncthreads();
    if (threadIdx.x == 0) {
        float sum = swarp[0] + swarp[1] + swarp[2] + swarp[3];
        atomicAdd(out, sum * (1.0f / ((float)BN * (float)BN)));
    }
}

// ---------------------------------------------------------------------------
extern "C" void kernel_launch(void* const* d_in, const int* in_sizes, int n_in,
                              void* d_out, int out_size) {
    const float* teacher = (const float*)d_in[0];
    const float* student = (const float*)d_in[1];
    const float* Wt = (const float*)d_in[2];
    const float* bt = (const float*)d_in[3];
    const float* Wsw = (const float*)d_in[4];
    const float* bs = (const float*)d_in[5];
    const float* W1 = (const float*)d_in[6];
    const float* b1 = (const float*)d_in[7];
    const float* W2 = (const float*)d_in[8];
    const float* b2 = (const float*)d_in[9];
    float* out = (float*)d_out;

    proj_gemm<<<dim3(32, 32, 2), 128>>>(teacher, Wt, student, Wsw);
    sumtp<<<128, 256>>>(bt, bs, out, out_size);
    uv_gemm<<<dim3(16, 4), 256>>>(W1, b1);
    pairwise_part<<<dim3(8, 16, 16), 128>>>(W2);
    reduce_kernel<<<512, 128>>>(b2, out);
}